// round 1
// baseline (speedup 1.0000x reference)
#include <cuda_runtime.h>
#include <math.h>

#define NTOK 8192
#define DIM  1024
#define NEXP 32
#define HID  128
#define TK   4
#define SHID 512

// ---------------- scratch (device globals; no allocations) ----------------
__device__ __align__(16) float g_logits[NTOK * NEXP];
__device__ __align__(16) int   g_topk_idx[NTOK * TK];
__device__ __align__(16) float g_topk_sc[NTOK * TK];
__device__ __align__(16) int   g_counts[NEXP];
__device__ __align__(16) int   g_offsets[NEXP + 1];
__device__ __align__(16) int   g_cursor[NEXP];
__device__ __align__(16) int   g_bucket_tok[NTOK * TK];
__device__ __align__(16) float g_bucket_sc[NTOK * TK];
__device__ __align__(16) int   g_tok_pos[NTOK * TK];
__device__ __align__(16) float g_Y[(size_t)NTOK * TK * DIM];   // 134 MB scratch
__device__ __align__(16) float g_Hs[(size_t)NTOK * SHID];      // 16 MB scratch

// ---------------- K0: zero the per-expert counters ----------------
__global__ void init_kernel() {
    int t = threadIdx.x;
    if (t < NEXP) { g_counts[t] = 0; g_cursor[t] = 0; }
}

// ---------------- K1: router logits  logits[n][e] = x[n]·rw[e] + rb[e] ----
__global__ __launch_bounds__(256) void router_kernel(
    const float* __restrict__ x, const float* __restrict__ rw,
    const float* __restrict__ rb) {
    __shared__ float xs[8 * DIM];
    int tok0 = blockIdx.x * 8;
    int t = threadIdx.x;
#pragma unroll
    for (int i = 0; i < 8; i++) {
        int s = t + i * 256;           // 2048 float4 slots
        int r = s >> 8; int q = s & 255;
        *(float4*)(xs + r * DIM + q * 4) =
            *(const float4*)(x + (size_t)(tok0 + r) * DIM + q * 4);
    }
    __syncthreads();
    int tl = t >> 5, e = t & 31;
    float acc = rb[e];
    const float4* xv = (const float4*)(xs + tl * DIM);
    const float4* wv = (const float4*)(rw + (size_t)e * DIM);
#pragma unroll 4
    for (int q = 0; q < DIM / 4; q++) {
        float4 a = xv[q], b = wv[q];
        acc = fmaf(a.x, b.x, acc); acc = fmaf(a.y, b.y, acc);
        acc = fmaf(a.z, b.z, acc); acc = fmaf(a.w, b.w, acc);
    }
    g_logits[(size_t)(tok0 + tl) * NEXP + e] = acc;
}

// ---------------- K2: softmax + top4 + renormalize (warp per token) -------
__global__ __launch_bounds__(256) void topk_kernel() {
    int warp = threadIdx.x >> 5;
    int lane = threadIdx.x & 31;
    int tok = blockIdx.x * 8 + warp;
    float l = g_logits[(size_t)tok * NEXP + lane];
    float m = l;
#pragma unroll
    for (int o = 16; o; o >>= 1) m = fmaxf(m, __shfl_xor_sync(~0u, m, o));
    float p = __expf(l - m);
    float s = p;
#pragma unroll
    for (int o = 16; o; o >>= 1) s += __shfl_xor_sync(~0u, s, o);
    float sc = p / s;

    float cs[TK]; int ci[TK];
    float cur = sc;
#pragma unroll
    for (int t = 0; t < TK; t++) {
        float v = cur; int vi = lane;
#pragma unroll
        for (int o = 16; o; o >>= 1) {
            float ov = __shfl_xor_sync(~0u, v, o);
            int   oi = __shfl_xor_sync(~0u, vi, o);
            if (ov > v || (ov == v && oi < vi)) { v = ov; vi = oi; }
        }
        cs[t] = v; ci[t] = vi;
        if (lane == vi) cur = -1.f;
    }
    float ssum = cs[0] + cs[1] + cs[2] + cs[3];
    float inv = 1.f / fmaxf(ssum, 1e-12f);
    if (lane < TK) {
        g_topk_idx[tok * TK + lane] = ci[lane];
        g_topk_sc [tok * TK + lane] = cs[lane] * inv;
        atomicAdd(&g_counts[ci[lane]], 1);
    }
}

// ---------------- K3: exclusive scan over 32 experts ----------------------
__global__ void scan_kernel() {
    if (threadIdx.x == 0) {
        int acc = 0;
        g_offsets[0] = 0;
        for (int e = 0; e < NEXP; e++) { acc += g_counts[e]; g_offsets[e + 1] = acc; }
    }
    __syncthreads();
    if (threadIdx.x < NEXP) g_cursor[threadIdx.x] = g_offsets[threadIdx.x];
}

// ---------------- K4: scatter (token,score) into expert buckets -----------
__global__ __launch_bounds__(256) void scatter_kernel() {
    int i = blockIdx.x * 256 + threadIdx.x;   // i < NTOK*TK
    int e = g_topk_idx[i];
    int pos = atomicAdd(&g_cursor[e], 1);
    g_bucket_tok[pos] = i >> 2;
    g_bucket_sc [pos] = g_topk_sc[i];
    g_tok_pos[i] = pos;
}

// ---------------- K5: fused grouped expert FFN ----------------------------
// block = (64-token tile, expert).  Phase A: G/U = X@gateT, X@upT (K=1024)
// Phase B: Hs = silu(G)*U in smem.  Phase C: Y = score * (Hs @ downT).
#define SMEM_FFN_BYTES ((64 * 132 + 128 * 132) * 4)
__global__ __launch_bounds__(256, 2) void expert_ffn_kernel(
    const float* __restrict__ x, const float* __restrict__ gw,
    const float* __restrict__ uw, const float* __restrict__ dw) {
    int e = blockIdx.y;
    int off = g_offsets[e];
    int cnt = g_offsets[e + 1] - off;
    int tile0 = blockIdx.x * 64;
    if (tile0 >= cnt) return;

    extern __shared__ float sm[];
    float* Hs = sm;                    // 64 x 132
    float* R  = sm + 64 * 132;         // workspace (phase A tiles / Dw)
    float* Xs = R;                     // 64 x 36
    float* Gs = R + 64 * 36;           // 128 x 36
    float* Us = Gs + 128 * 36;         // 128 x 36

    int t = threadIdx.x;
    int m0 = (t >> 4) * 4, n0 = (t & 15) * 8;

    int gtok[2]; bool lval[2];
#pragma unroll
    for (int i = 0; i < 2; i++) {
        int s = t + i * 256; int r = s >> 3;
        int m = tile0 + r;
        lval[i] = m < cnt;
        gtok[i] = lval[i] ? g_bucket_tok[off + m] : 0;
    }

    float ag[4][8] = {}, au[4][8] = {};
    const float* gb = gw + (size_t)e * HID * DIM;
    const float* ub = uw + (size_t)e * HID * DIM;

    for (int kb = 0; kb < DIM; kb += 32) {
#pragma unroll
        for (int i = 0; i < 2; i++) {
            int s = t + i * 256; int r = s >> 3; int q = s & 7;
            float4 v = make_float4(0.f, 0.f, 0.f, 0.f);
            if (lval[i]) v = *(const float4*)(x + (size_t)gtok[i] * DIM + kb + q * 4);
            *(float4*)(Xs + r * 36 + q * 4) = v;
        }
#pragma unroll
        for (int i = 0; i < 4; i++) {
            int s = t + i * 256; int h = s >> 3; int q = s & 7;
            *(float4*)(Gs + h * 36 + q * 4) = *(const float4*)(gb + (size_t)h * DIM + kb + q * 4);
            *(float4*)(Us + h * 36 + q * 4) = *(const float4*)(ub + (size_t)h * DIM + kb + q * 4);
        }
        __syncthreads();
#pragma unroll 8
        for (int k = 0; k < 32; k++) {
            float a[4], bg[8], bu[8];
#pragma unroll
            for (int i = 0; i < 4; i++) a[i] = Xs[(m0 + i) * 36 + k];
#pragma unroll
            for (int j = 0; j < 8; j++) { bg[j] = Gs[(n0 + j) * 36 + k]; bu[j] = Us[(n0 + j) * 36 + k]; }
#pragma unroll
            for (int i = 0; i < 4; i++)
#pragma unroll
                for (int j = 0; j < 8; j++) {
                    ag[i][j] = fmaf(a[i], bg[j], ag[i][j]);
                    au[i][j] = fmaf(a[i], bu[j], au[i][j]);
                }
        }
        __syncthreads();
    }

    // Phase B: SiLU(g)*u into Hs
#pragma unroll
    for (int i = 0; i < 4; i++)
#pragma unroll
        for (int j = 0; j < 8; j++) {
            float g = ag[i][j];
            Hs[(m0 + i) * 132 + n0 + j] = g / (1.f + __expf(-g)) * au[i][j];
        }
    __syncthreads();

    // Phase C: down GEMM, scaled write to Y
    float sc[4]; int pr[4]; bool rv[4];
#pragma unroll
    for (int i = 0; i < 4; i++) {
        int m = tile0 + m0 + i;
        rv[i] = m < cnt;
        pr[i] = rv[i] ? off + m : 0;
        sc[i] = rv[i] ? g_bucket_sc[off + m] : 0.f;
    }
    const float* db = dw + (size_t)e * DIM * HID;
    float* Dw = R;   // 128 x 132

    for (int d0 = 0; d0 < DIM; d0 += 128) {
#pragma unroll
        for (int i = 0; i < 16; i++) {
            int s = t + i * 256; int d = s >> 5; int q = s & 31;
            *(float4*)(Dw + d * 132 + q * 4) =
                *(const float4*)(db + (size_t)(d0 + d) * HID + q * 4);
        }
        __syncthreads();
        float acc[4][8] = {};
#pragma unroll 8
        for (int h = 0; h < 128; h++) {
            float a[4], b[8];
#pragma unroll
            for (int i = 0; i < 4; i++) a[i] = Hs[(m0 + i) * 132 + h];
#pragma unroll
            for (int j = 0; j < 8; j++) b[j] = Dw[(n0 + j) * 132 + h];
#pragma unroll
            for (int i = 0; i < 4; i++)
#pragma unroll
                for (int j = 0; j < 8; j++) acc[i][j] = fmaf(a[i], b[j], acc[i][j]);
        }
#pragma unroll
        for (int i = 0; i < 4; i++) if (rv[i]) {
            size_t base = (size_t)pr[i] * DIM + d0 + n0;
            float4 v0 = make_float4(acc[i][0] * sc[i], acc[i][1] * sc[i],
                                    acc[i][2] * sc[i], acc[i][3] * sc[i]);
            float4 v1 = make_float4(acc[i][4] * sc[i], acc[i][5] * sc[i],
                                    acc[i][6] * sc[i], acc[i][7] * sc[i]);
            *(float4*)(g_Y + base)     = v0;
            *(float4*)(g_Y + base + 4) = v1;
        }
        __syncthreads();
    }
}

// ---------------- K6: shared expert gate/up (dense GEMM) ------------------
__global__ __launch_bounds__(256) void shared_gateup_kernel(
    const float* __restrict__ x, const float* __restrict__ gw,
    const float* __restrict__ uw) {
    __shared__ float Xs[64 * 36], Gs[128 * 36], Us[128 * 36];
    int tile0 = blockIdx.x * 64;
    int hb = blockIdx.y * 128;
    int t = threadIdx.x;
    int m0 = (t >> 4) * 4, n0 = (t & 15) * 8;
    float ag[4][8] = {}, au[4][8] = {};
    const float* gb = gw + (size_t)hb * DIM;
    const float* ub = uw + (size_t)hb * DIM;

    for (int kb = 0; kb < DIM; kb += 32) {
#pragma unroll
        for (int i = 0; i < 2; i++) {
            int s = t + i * 256; int r = s >> 3; int q = s & 7;
            *(float4*)(Xs + r * 36 + q * 4) =
                *(const float4*)(x + (size_t)(tile0 + r) * DIM + kb + q * 4);
        }
#pragma unroll
        for (int i = 0; i < 4; i++) {
            int s = t + i * 256; int h = s >> 3; int q = s & 7;
            *(float4*)(Gs + h * 36 + q * 4) = *(const float4*)(gb + (size_t)h * DIM + kb + q * 4);
            *(float4*)(Us + h * 36 + q * 4) = *(const float4*)(ub + (size_t)h * DIM + kb + q * 4);
        }
        __syncthreads();
#pragma unroll 8
        for (int k = 0; k < 32; k++) {
            float a[4], bg[8], bu[8];
#pragma unroll
            for (int i = 0; i < 4; i++) a[i] = Xs[(m0 + i) * 36 + k];
#pragma unroll
            for (int j = 0; j < 8; j++) { bg[j] = Gs[(n0 + j) * 36 + k]; bu[j] = Us[(n0 + j) * 36 + k]; }
#pragma unroll
            for (int i = 0; i < 4; i++)
#pragma unroll
                for (int j = 0; j < 8; j++) {
                    ag[i][j] = fmaf(a[i], bg[j], ag[i][j]);
                    au[i][j] = fmaf(a[i], bu[j], au[i][j]);
                }
        }
        __syncthreads();
    }
#pragma unroll
    for (int i = 0; i < 4; i++)
#pragma unroll
        for (int j = 0; j < 8; j++) {
            float g = ag[i][j];
            g_Hs[(size_t)(tile0 + m0 + i) * SHID + hb + n0 + j] =
                g / (1.f + __expf(-g)) * au[i][j];
        }
}

// ---------------- K7: out = Hs @ sdownT + sum_k Y[tok_pos[n,k]] -----------
__global__ __launch_bounds__(256) void final_kernel(
    const float* __restrict__ sdw, float* __restrict__ out) {
    __shared__ float As[64 * 36], Bs[128 * 36];
    int tile0 = blockIdx.x * 64;
    int d0g = blockIdx.y * 128;
    int t = threadIdx.x;
    int m0 = (t >> 4) * 4, n0 = (t & 15) * 8;
    float acc[4][8] = {};

    for (int kb = 0; kb < SHID; kb += 32) {
#pragma unroll
        for (int i = 0; i < 2; i++) {
            int s = t + i * 256; int r = s >> 3; int q = s & 7;
            *(float4*)(As + r * 36 + q * 4) =
                *(const float4*)(g_Hs + (size_t)(tile0 + r) * SHID + kb + q * 4);
        }
#pragma unroll
        for (int i = 0; i < 4; i++) {
            int s = t + i * 256; int d = s >> 3; int q = s & 7;
            *(float4*)(Bs + d * 36 + q * 4) =
                *(const float4*)(sdw + (size_t)(d0g + d) * SHID + kb + q * 4);
        }
        __syncthreads();
#pragma unroll 8
        for (int k = 0; k < 32; k++) {
            float a[4], b[8];
#pragma unroll
            for (int i = 0; i < 4; i++) a[i] = As[(m0 + i) * 36 + k];
#pragma unroll
            for (int j = 0; j < 8; j++) b[j] = Bs[(n0 + j) * 36 + k];
#pragma unroll
            for (int i = 0; i < 4; i++)
#pragma unroll
                for (int j = 0; j < 8; j++) acc[i][j] = fmaf(a[i], b[j], acc[i][j]);
        }
        __syncthreads();
    }

#pragma unroll
    for (int i = 0; i < 4; i++) {
        int tok = tile0 + m0 + i;
        int4 tp = *(const int4*)(g_tok_pos + tok * TK);
        size_t ob = (size_t)tok * DIM + d0g + n0;
#pragma unroll
        for (int jj = 0; jj < 2; jj++) {
            size_t col = (size_t)(d0g + n0 + jj * 4);
            float4 y0 = *(const float4*)(g_Y + (size_t)tp.x * DIM + col);
            float4 y1 = *(const float4*)(g_Y + (size_t)tp.y * DIM + col);
            float4 y2 = *(const float4*)(g_Y + (size_t)tp.z * DIM + col);
            float4 y3 = *(const float4*)(g_Y + (size_t)tp.w * DIM + col);
            float4 r;
            r.x = acc[i][jj * 4 + 0] + y0.x + y1.x + y2.x + y3.x;
            r.y = acc[i][jj * 4 + 1] + y0.y + y1.y + y2.y + y3.y;
            r.z = acc[i][jj * 4 + 2] + y0.z + y1.z + y2.z + y3.z;
            r.w = acc[i][jj * 4 + 3] + y0.w + y1.w + y2.w + y3.w;
            *(float4*)(out + ob + jj * 4) = r;
        }
    }
}

// ---------------- launch ---------------------------------------------------
extern "C" void kernel_launch(void* const* d_in, const int* in_sizes, int n_in,
                              void* d_out, int out_size) {
    const float* x   = (const float*)d_in[0];
    const float* rw  = (const float*)d_in[1];
    const float* rb  = (const float*)d_in[2];
    const float* gw  = (const float*)d_in[3];
    const float* uw  = (const float*)d_in[4];
    const float* dw  = (const float*)d_in[5];
    const float* sgw = (const float*)d_in[6];
    const float* suw = (const float*)d_in[7];
    const float* sdw = (const float*)d_in[8];
    float* out = (float*)d_out;

    cudaFuncSetAttribute(expert_ffn_kernel,
                         cudaFuncAttributeMaxDynamicSharedMemorySize, SMEM_FFN_BYTES);

    init_kernel<<<1, 32>>>();
    router_kernel<<<NTOK / 8, 256>>>(x, rw, rb);
    topk_kernel<<<NTOK / 8, 256>>>();
    scan_kernel<<<1, 32>>>();
    scatter_kernel<<<NTOK * TK / 256, 256>>>();
    expert_ffn_kernel<<<dim3(NTOK / 64, NEXP), 256, SMEM_FFN_BYTES>>>(x, gw, uw, dw);
    shared_gateup_kernel<<<dim3(NTOK / 64, SHID / 128), 256>>>(x, sgw, suw);
    final_kernel<<<dim3(NTOK / 64, DIM / 128), 256>>>(sdw, out);
}

// round 2
// speedup vs baseline: 12.8471x; 12.8471x over previous
#include <cuda_runtime.h>
#include <math.h>
#include <stdint.h>

#define NTOK 8192
#define DIM  1024
#define NEXP 32
#define HID  128
#define TK   4
#define SHID 512
#define NROWS (NTOK*TK)

// ---------------- scratch (device globals; no allocations) ----------------
__device__ __align__(16) float g_logits[NTOK * NEXP];
__device__ __align__(16) int   g_topk_idx[NROWS];
__device__ __align__(16) float g_topk_sc[NROWS];
__device__ __align__(16) int   g_counts[NEXP];
__device__ __align__(16) int   g_offsets[NEXP + 1];
__device__ __align__(16) int   g_cursor[NEXP];
__device__ __align__(16) int   g_bucket_tok[NROWS];
__device__ __align__(16) float g_bucket_sc[NROWS];
__device__ __align__(16) int   g_tok_pos[NROWS];
__device__ __align__(16) float g_G[(size_t)NROWS * HID];
__device__ __align__(16) float g_U[(size_t)NROWS * HID];
__device__ __align__(16) float g_H[(size_t)NROWS * HID];
__device__ __align__(16) float g_sG[(size_t)NTOK * SHID];
__device__ __align__(16) float g_sU[(size_t)NTOK * SHID];
__device__ __align__(16) float g_sH[(size_t)NTOK * SHID];
__device__ __align__(16) float g_Y[(size_t)NROWS * DIM];

// ---------------- tf32 mma helpers ----------------------------------------
__device__ __forceinline__ uint32_t f2tf(float x) {
    uint32_t r; asm("cvt.rna.tf32.f32 %0, %1;" : "=r"(r) : "f"(x)); return r;
}
__device__ __forceinline__ void st_tile(uint32_t* dst, float4 v) {
    uint4 u; u.x = f2tf(v.x); u.y = f2tf(v.y); u.z = f2tf(v.z); u.w = f2tf(v.w);
    *(uint4*)dst = u;
}
__device__ __forceinline__ void mma8(float* c, const uint32_t* a, const uint32_t* b) {
    asm volatile(
        "mma.sync.aligned.m16n8k8.row.col.f32.tf32.tf32.f32 "
        "{%0,%1,%2,%3}, {%4,%5,%6,%7}, {%8,%9}, {%0,%1,%2,%3};"
        : "+f"(c[0]), "+f"(c[1]), "+f"(c[2]), "+f"(c[3])
        : "r"(a[0]), "r"(a[1]), "r"(a[2]), "r"(a[3]), "r"(b[0]), "r"(b[1]));
}

// 128x128 block tile, 8 warps (4m x 2n), warp tile 32x64, k-step 32.
// Smem tiles stored [row][k] with stride 36 -> conflict-free fragment loads.
__device__ __forceinline__ void compute_k32(
    const uint32_t* __restrict__ As, const uint32_t* __restrict__ Bs,
    int wm, int wn, int g, int tig, float acc[2][8][4]) {
#pragma unroll
    for (int ks = 0; ks < 4; ks++) {
        int k0 = ks * 8;
        uint32_t af[2][4];
#pragma unroll
        for (int mt = 0; mt < 2; mt++) {
            int r = wm + mt * 16 + g;
            af[mt][0] = As[r * 36 + k0 + tig];
            af[mt][1] = As[(r + 8) * 36 + k0 + tig];
            af[mt][2] = As[r * 36 + k0 + tig + 4];
            af[mt][3] = As[(r + 8) * 36 + k0 + tig + 4];
        }
        uint32_t bf[8][2];
#pragma unroll
        for (int nt = 0; nt < 8; nt++) {
            int cn = wn + nt * 8 + g;
            bf[nt][0] = Bs[cn * 36 + k0 + tig];
            bf[nt][1] = Bs[cn * 36 + k0 + tig + 4];
        }
#pragma unroll
        for (int mt = 0; mt < 2; mt++)
#pragma unroll
            for (int nt = 0; nt < 8; nt++) mma8(acc[mt][nt], af[mt], bf[nt]);
    }
}

// ---------------- K0: init counters ----------------------------------------
__global__ void init_kernel() {
    int t = threadIdx.x;
    if (t < NEXP) { g_counts[t] = 0; g_cursor[t] = 0; }
}

// ---------------- K1: router logits (fp32 SIMT, exact routing) -------------
__global__ __launch_bounds__(256) void router_kernel(
    const float* __restrict__ x, const float* __restrict__ rw,
    const float* __restrict__ rb) {
    __shared__ float xs[8 * DIM];
    int tok0 = blockIdx.x * 8;
    int t = threadIdx.x;
#pragma unroll
    for (int i = 0; i < 8; i++) {
        int s = t + i * 256;
        int r = s >> 8; int q = s & 255;
        *(float4*)(xs + r * DIM + q * 4) =
            *(const float4*)(x + (size_t)(tok0 + r) * DIM + q * 4);
    }
    __syncthreads();
    int tl = t >> 5, e = t & 31;
    float acc = rb[e];
    const float4* xv = (const float4*)(xs + tl * DIM);
    const float4* wv = (const float4*)(rw + (size_t)e * DIM);
#pragma unroll 4
    for (int q = 0; q < DIM / 4; q++) {
        float4 a = xv[q], b = wv[q];
        acc = fmaf(a.x, b.x, acc); acc = fmaf(a.y, b.y, acc);
        acc = fmaf(a.z, b.z, acc); acc = fmaf(a.w, b.w, acc);
    }
    g_logits[(size_t)(tok0 + tl) * NEXP + e] = acc;
}

// ---------------- K2: softmax + top4 + renormalize --------------------------
__global__ __launch_bounds__(256) void topk_kernel() {
    int warp = threadIdx.x >> 5;
    int lane = threadIdx.x & 31;
    int tok = blockIdx.x * 8 + warp;
    float l = g_logits[(size_t)tok * NEXP + lane];
    float m = l;
#pragma unroll
    for (int o = 16; o; o >>= 1) m = fmaxf(m, __shfl_xor_sync(~0u, m, o));
    float p = __expf(l - m);
    float s = p;
#pragma unroll
    for (int o = 16; o; o >>= 1) s += __shfl_xor_sync(~0u, s, o);
    float sc = p / s;

    float cs[TK]; int ci[TK];
    float cur = sc;
#pragma unroll
    for (int t = 0; t < TK; t++) {
        float v = cur; int vi = lane;
#pragma unroll
        for (int o = 16; o; o >>= 1) {
            float ov = __shfl_xor_sync(~0u, v, o);
            int   oi = __shfl_xor_sync(~0u, vi, o);
            if (ov > v || (ov == v && oi < vi)) { v = ov; vi = oi; }
        }
        cs[t] = v; ci[t] = vi;
        if (lane == vi) cur = -1.f;
    }
    float ssum = cs[0] + cs[1] + cs[2] + cs[3];
    float inv = 1.f / fmaxf(ssum, 1e-12f);
    if (lane < TK) {
        g_topk_idx[tok * TK + lane] = ci[lane];
        g_topk_sc [tok * TK + lane] = cs[lane] * inv;
        atomicAdd(&g_counts[ci[lane]], 1);
    }
}

// ---------------- K3: scan ---------------------------------------------------
__global__ void scan_kernel() {
    if (threadIdx.x == 0) {
        int acc = 0;
        g_offsets[0] = 0;
        for (int e = 0; e < NEXP; e++) { acc += g_counts[e]; g_offsets[e + 1] = acc; }
    }
    __syncthreads();
    if (threadIdx.x < NEXP) g_cursor[threadIdx.x] = g_offsets[threadIdx.x];
}

// ---------------- K4: scatter ------------------------------------------------
__global__ __launch_bounds__(256) void scatter_kernel() {
    int i = blockIdx.x * 256 + threadIdx.x;
    int e = g_topk_idx[i];
    int pos = atomicAdd(&g_cursor[e], 1);
    g_bucket_tok[pos] = i >> 2;
    g_bucket_sc [pos] = g_topk_sc[i];
    g_tok_pos[i] = pos;
}

// ---------------- K5: routed gate/up GEMM (tf32, gather-A) ------------------
// grid (64, NEXP, 2)   z: 0=gate, 1=up.   C[m,128] = Xg[m,1024] @ W^T
__global__ __launch_bounds__(256) void moe_gu_kernel(
    const float* __restrict__ x, const float* __restrict__ gw,
    const float* __restrict__ uw) {
    int e = blockIdx.y;
    int off = g_offsets[e], cnt = g_offsets[e + 1] - off;
    int tile0 = blockIdx.x * 128;
    if (tile0 >= cnt) return;
    const float* W = (blockIdx.z == 0 ? gw : uw) + (size_t)e * HID * DIM;
    float* OUT = (blockIdx.z == 0 ? g_G : g_U);
    __shared__ uint32_t As[128 * 36], Bs[128 * 36];
    __shared__ int toks[128];
    int t = threadIdx.x;
    if (t < 128) { int m = tile0 + t; toks[t] = (m < cnt) ? g_bucket_tok[off + m] : -1; }
    __syncthreads();
    int lane = t & 31, wid = t >> 5;
    int wm = (wid & 3) * 32, wn = (wid >> 2) * 64, g = lane >> 2, tig = lane & 3;
    float acc[2][8][4] = {};
    for (int kb = 0; kb < DIM; kb += 32) {
#pragma unroll
        for (int i = 0; i < 4; i++) {
            int s = t + i * 256; int r = s >> 3, q = s & 7;
            int tok = toks[r];
            float4 v = make_float4(0.f, 0.f, 0.f, 0.f);
            if (tok >= 0) v = *(const float4*)(x + (size_t)tok * DIM + kb + q * 4);
            st_tile(As + r * 36 + q * 4, v);
            st_tile(Bs + r * 36 + q * 4, *(const float4*)(W + (size_t)r * DIM + kb + q * 4));
        }
        __syncthreads();
        compute_k32(As, Bs, wm, wn, g, tig, acc);
        __syncthreads();
    }
#pragma unroll
    for (int mt = 0; mt < 2; mt++) {
        int rA = tile0 + wm + mt * 16 + g;
#pragma unroll
        for (int nt = 0; nt < 8; nt++) {
            int col = wn + nt * 8 + 2 * tig;
            if (rA < cnt)
                *(float2*)(OUT + (size_t)(off + rA) * HID + col) =
                    make_float2(acc[mt][nt][0], acc[mt][nt][1]);
            if (rA + 8 < cnt)
                *(float2*)(OUT + (size_t)(off + rA + 8) * HID + col) =
                    make_float2(acc[mt][nt][2], acc[mt][nt][3]);
        }
    }
}

// ---------------- K6: elementwise SiLU(g)*u  (which: 0=routed, 1=shared) ----
__global__ __launch_bounds__(256) void act_kernel(int which) {
    size_t i = (size_t)blockIdx.x * 256 + threadIdx.x;
    const float4* G = which ? (const float4*)g_sG : (const float4*)g_G;
    const float4* U = which ? (const float4*)g_sU : (const float4*)g_U;
    float4* H = which ? (float4*)g_sH : (float4*)g_H;
    float4 gv = G[i], uv = U[i], h;
    h.x = gv.x / (1.f + __expf(-gv.x)) * uv.x;
    h.y = gv.y / (1.f + __expf(-gv.y)) * uv.y;
    h.z = gv.z / (1.f + __expf(-gv.z)) * uv.z;
    h.w = gv.w / (1.f + __expf(-gv.w)) * uv.w;
    H[i] = h;
}

// ---------------- K7: routed down GEMM (tf32), scaled -> Y ------------------
// grid (64, 8, NEXP)
__global__ __launch_bounds__(256) void moe_down_kernel(const float* __restrict__ dw) {
    int e = blockIdx.z;
    int off = g_offsets[e], cnt = g_offsets[e + 1] - off;
    int tile0 = blockIdx.x * 128;
    if (tile0 >= cnt) return;
    int nb = blockIdx.y * 128;
    const float* W = dw + (size_t)e * DIM * HID;
    __shared__ uint32_t As[128 * 36], Bs[128 * 36];
    __shared__ float scs[128];
    int t = threadIdx.x;
    if (t < 128) { int m = tile0 + t; scs[t] = (m < cnt) ? g_bucket_sc[off + m] : 0.f; }
    int lane = t & 31, wid = t >> 5;
    int wm = (wid & 3) * 32, wn = (wid >> 2) * 64, g = lane >> 2, tig = lane & 3;
    float acc[2][8][4] = {};
    for (int kb = 0; kb < HID; kb += 32) {
#pragma unroll
        for (int i = 0; i < 4; i++) {
            int s = t + i * 256; int r = s >> 3, q = s & 7;
            int m = tile0 + r;
            float4 v = make_float4(0.f, 0.f, 0.f, 0.f);
            if (m < cnt) v = *(const float4*)(g_H + (size_t)(off + m) * HID + kb + q * 4);
            st_tile(As + r * 36 + q * 4, v);
            st_tile(Bs + r * 36 + q * 4, *(const float4*)(W + (size_t)(nb + r) * HID + kb + q * 4));
        }
        __syncthreads();
        compute_k32(As, Bs, wm, wn, g, tig, acc);
        __syncthreads();
    }
#pragma unroll
    for (int mt = 0; mt < 2; mt++) {
        int rL = wm + mt * 16 + g;
        int rA = tile0 + rL;
#pragma unroll
        for (int nt = 0; nt < 8; nt++) {
            int col = nb + wn + nt * 8 + 2 * tig;
            if (rA < cnt) {
                float s = scs[rL];
                *(float2*)(g_Y + (size_t)(off + rA) * DIM + col) =
                    make_float2(acc[mt][nt][0] * s, acc[mt][nt][1] * s);
            }
            if (rA + 8 < cnt) {
                float s = scs[rL + 8];
                *(float2*)(g_Y + (size_t)(off + rA + 8) * DIM + col) =
                    make_float2(acc[mt][nt][2] * s, acc[mt][nt][3] * s);
            }
        }
    }
}

// ---------------- K8: shared gate/up GEMM (tf32) ----------------------------
// grid (64, 4, 2)
__global__ __launch_bounds__(256) void shared_gu_kernel(
    const float* __restrict__ x, const float* __restrict__ sgw,
    const float* __restrict__ suw) {
    int tile0 = blockIdx.x * 128;
    int nb = blockIdx.y * 128;
    const float* W = (blockIdx.z == 0 ? sgw : suw);
    float* OUT = (blockIdx.z == 0 ? g_sG : g_sU);
    __shared__ uint32_t As[128 * 36], Bs[128 * 36];
    int t = threadIdx.x, lane = t & 31, wid = t >> 5;
    int wm = (wid & 3) * 32, wn = (wid >> 2) * 64, g = lane >> 2, tig = lane & 3;
    float acc[2][8][4] = {};
    for (int kb = 0; kb < DIM; kb += 32) {
#pragma unroll
        for (int i = 0; i < 4; i++) {
            int s = t + i * 256; int r = s >> 3, q = s & 7;
            st_tile(As + r * 36 + q * 4, *(const float4*)(x + (size_t)(tile0 + r) * DIM + kb + q * 4));
            st_tile(Bs + r * 36 + q * 4, *(const float4*)(W + (size_t)(nb + r) * DIM + kb + q * 4));
        }
        __syncthreads();
        compute_k32(As, Bs, wm, wn, g, tig, acc);
        __syncthreads();
    }
#pragma unroll
    for (int mt = 0; mt < 2; mt++) {
        int rA = tile0 + wm + mt * 16 + g;
#pragma unroll
        for (int nt = 0; nt < 8; nt++) {
            int col = nb + wn + nt * 8 + 2 * tig;
            *(float2*)(OUT + (size_t)rA * SHID + col) = make_float2(acc[mt][nt][0], acc[mt][nt][1]);
            *(float2*)(OUT + (size_t)(rA + 8) * SHID + col) = make_float2(acc[mt][nt][2], acc[mt][nt][3]);
        }
    }
}

// ---------------- K9: final GEMM + Y gather ----------------------------------
// grid (64, 8): out = sH @ sdw^T + sum_k Y[tok_pos[n,k]]
__global__ __launch_bounds__(256) void final_kernel(
    const float* __restrict__ sdw, float* __restrict__ out) {
    int tile0 = blockIdx.x * 128;
    int nb = blockIdx.y * 128;
    __shared__ uint32_t As[128 * 36], Bs[128 * 36];
    int t = threadIdx.x, lane = t & 31, wid = t >> 5;
    int wm = (wid & 3) * 32, wn = (wid >> 2) * 64, g = lane >> 2, tig = lane & 3;
    float acc[2][8][4] = {};
    for (int kb = 0; kb < SHID; kb += 32) {
#pragma unroll
        for (int i = 0; i < 4; i++) {
            int s = t + i * 256; int r = s >> 3, q = s & 7;
            st_tile(As + r * 36 + q * 4, *(const float4*)(g_sH + (size_t)(tile0 + r) * SHID + kb + q * 4));
            st_tile(Bs + r * 36 + q * 4, *(const float4*)(sdw + (size_t)(nb + r) * SHID + kb + q * 4));
        }
        __syncthreads();
        compute_k32(As, Bs, wm, wn, g, tig, acc);
        __syncthreads();
    }
#pragma unroll
    for (int mt = 0; mt < 2; mt++) {
        int r0 = tile0 + wm + mt * 16 + g;
        int4 tpa = *(const int4*)(g_tok_pos + r0 * TK);
        int4 tpb = *(const int4*)(g_tok_pos + (r0 + 8) * TK);
#pragma unroll
        for (int nt = 0; nt < 8; nt++) {
            int col = nb + wn + nt * 8 + 2 * tig;
            float2 y0 = *(const float2*)(g_Y + (size_t)tpa.x * DIM + col);
            float2 y1 = *(const float2*)(g_Y + (size_t)tpa.y * DIM + col);
            float2 y2 = *(const float2*)(g_Y + (size_t)tpa.z * DIM + col);
            float2 y3 = *(const float2*)(g_Y + (size_t)tpa.w * DIM + col);
            float2 ra;
            ra.x = acc[mt][nt][0] + y0.x + y1.x + y2.x + y3.x;
            ra.y = acc[mt][nt][1] + y0.y + y1.y + y2.y + y3.y;
            *(float2*)(out + (size_t)r0 * DIM + col) = ra;
            float2 z0 = *(const float2*)(g_Y + (size_t)tpb.x * DIM + col);
            float2 z1 = *(const float2*)(g_Y + (size_t)tpb.y * DIM + col);
            float2 z2 = *(const float2*)(g_Y + (size_t)tpb.z * DIM + col);
            float2 z3 = *(const float2*)(g_Y + (size_t)tpb.w * DIM + col);
            float2 rb;
            rb.x = acc[mt][nt][2] + z0.x + z1.x + z2.x + z3.x;
            rb.y = acc[mt][nt][3] + z0.y + z1.y + z2.y + z3.y;
            *(float2*)(out + (size_t)(r0 + 8) * DIM + col) = rb;
        }
    }
}

// ---------------- launch ------------------------------------------------------
extern "C" void kernel_launch(void* const* d_in, const int* in_sizes, int n_in,
                              void* d_out, int out_size) {
    const float* x   = (const float*)d_in[0];
    const float* rw  = (const float*)d_in[1];
    const float* rb  = (const float*)d_in[2];
    const float* gw  = (const float*)d_in[3];
    const float* uw  = (const float*)d_in[4];
    const float* dw  = (const float*)d_in[5];
    const float* sgw = (const float*)d_in[6];
    const float* suw = (const float*)d_in[7];
    const float* sdw = (const float*)d_in[8];
    float* out = (float*)d_out;

    init_kernel<<<1, 32>>>();
    router_kernel<<<NTOK / 8, 256>>>(x, rw, rb);
    topk_kernel<<<NTOK / 8, 256>>>();
    scan_kernel<<<1, 32>>>();
    scatter_kernel<<<NROWS / 256, 256>>>();
    moe_gu_kernel<<<dim3(64, NEXP, 2), 256>>>(x, gw, uw);
    act_kernel<<<(NROWS * HID) / 4 / 256, 256>>>(0);
    moe_down_kernel<<<dim3(64, 8, NEXP), 256>>>(dw);
    shared_gu_kernel<<<dim3(64, 4, 2), 256>>>(x, sgw, suw);
    act_kernel<<<((size_t)NTOK * SHID) / 4 / 256, 256>>>(1);
    final_kernel<<<dim3(64, 8), 256>>>(sdw, out);
}

// round 3
// speedup vs baseline: 13.5630x; 1.0557x over previous
#include <cuda_runtime.h>
#include <math.h>
#include <stdint.h>

#define NTOK 8192
#define DIM  1024
#define NEXP 32
#define HID  128
#define TK   4
#define SHID 512
#define NROWS (NTOK*TK)

// ---------------- scratch (device globals; no allocations) ----------------
__device__ __align__(16) float g_logits[NTOK * NEXP];
__device__ __align__(16) int   g_topk_idx[NROWS];
__device__ __align__(16) float g_topk_sc[NROWS];
__device__ __align__(16) int   g_counts[NEXP];
__device__ __align__(16) int   g_offsets[NEXP + 1];
__device__ __align__(16) int   g_cursor[NEXP];
__device__ __align__(16) int   g_bucket_tok[NROWS];
__device__ __align__(16) float g_bucket_sc[NROWS];
__device__ __align__(16) int   g_tok_pos[NROWS];
__device__ __align__(16) float g_G[(size_t)NROWS * HID];
__device__ __align__(16) float g_U[(size_t)NROWS * HID];
__device__ __align__(16) float g_H[(size_t)NROWS * HID];
__device__ __align__(16) float g_sG[(size_t)NTOK * SHID];
__device__ __align__(16) float g_sU[(size_t)NTOK * SHID];
__device__ __align__(16) float g_sH[(size_t)NTOK * SHID];
__device__ __align__(16) float g_Y[(size_t)NROWS * DIM];

// ---------------- helpers ---------------------------------------------------
__device__ __forceinline__ uint32_t f2tf(float x) {
    uint32_t r; asm("cvt.rna.tf32.f32 %0, %1;" : "=r"(r) : "f"(x)); return r;
}
__device__ __forceinline__ uint32_t s2u(const void* p) {
    uint32_t r;
    asm("{.reg .u64 t; cvta.to.shared.u64 t, %1; cvt.u32.u64 %0, t;}" : "=r"(r) : "l"(p));
    return r;
}
__device__ __forceinline__ void cpa16(uint32_t daddr, const float* src, bool pred) {
    int sz = pred ? 16 : 0;
    asm volatile("cp.async.cg.shared.global [%0], [%1], 16, %2;\n"
                 :: "r"(daddr), "l"(src), "r"(sz));
}
__device__ __forceinline__ void cp_commit() {
    asm volatile("cp.async.commit_group;\n" ::);
}
template<int N> __device__ __forceinline__ void cp_wait() {
    asm volatile("cp.async.wait_group %0;\n" :: "n"(N));
}
__device__ __forceinline__ void mma8(float* c, const uint32_t* a, const uint32_t* b) {
    asm volatile(
        "mma.sync.aligned.m16n8k8.row.col.f32.tf32.tf32.f32 "
        "{%0,%1,%2,%3}, {%4,%5,%6,%7}, {%8,%9}, {%0,%1,%2,%3};"
        : "+f"(c[0]), "+f"(c[1]), "+f"(c[2]), "+f"(c[3])
        : "r"(a[0]), "r"(a[1]), "r"(a[2]), "r"(a[3]), "r"(b[0]), "r"(b[1]));
}

// 128x128 block tile, 8 warps (4m x 2n), warp tile 32x64, k-step 32.
// Smem raw fp32 [row][k], stride 36 (conflict-free); tf32 cvt at fragment load.
__device__ __forceinline__ void compute_k32f(
    const float* __restrict__ As, const float* __restrict__ Bs,
    int wm, int wn, int g, int tig, float acc[2][8][4]) {
#pragma unroll
    for (int ks = 0; ks < 4; ks++) {
        int k0 = ks * 8;
        uint32_t af[2][4];
#pragma unroll
        for (int mt = 0; mt < 2; mt++) {
            int r = wm + mt * 16 + g;
            af[mt][0] = f2tf(As[r * 36 + k0 + tig]);
            af[mt][1] = f2tf(As[(r + 8) * 36 + k0 + tig]);
            af[mt][2] = f2tf(As[r * 36 + k0 + tig + 4]);
            af[mt][3] = f2tf(As[(r + 8) * 36 + k0 + tig + 4]);
        }
        uint32_t bf[8][2];
#pragma unroll
        for (int nt = 0; nt < 8; nt++) {
            int cn = wn + nt * 8 + g;
            bf[nt][0] = f2tf(Bs[cn * 36 + k0 + tig]);
            bf[nt][1] = f2tf(Bs[cn * 36 + k0 + tig + 4]);
        }
#pragma unroll
        for (int mt = 0; mt < 2; mt++)
#pragma unroll
            for (int nt = 0; nt < 8; nt++) mma8(acc[mt][nt], af[mt], bf[nt]);
    }
}

// stage layout (floats): A0 [0,4608) A1 [4608,9216) B0 [9216,13824) B1 [13824,18432)
#define STAGE_F 4608
#define SMEM_PIPE_BYTES (4 * STAGE_F * 4)

__device__ __forceinline__ void issue_stage(
    uint32_t sAbase, uint32_t sBbase, int stage,
    const int* rr, const int* qq,
    const float* const* aP, const bool* av, const float* const* bP, int kb) {
    uint32_t so = (uint32_t)stage * STAGE_F * 4;
#pragma unroll
    for (int i = 0; i < 4; i++) {
        uint32_t o = (uint32_t)((rr[i] * 36 + qq[i] * 4) * 4);
        cpa16(sAbase + so + o, aP[i] + kb, av[i]);
        cpa16(sBbase + so + o, bP[i] + kb, true);
    }
    cp_commit();
}

// pipelined mainloop shared by all GEMM kernels
#define PIPE_LOOP(NITER)                                                        \
    issue_stage(sA, sB, 0, rr, qq, aP, av, bP, 0);                              \
    for (int it = 0; it < (NITER); it++) {                                      \
        if (it + 1 < (NITER))                                                   \
            issue_stage(sA, sB, (it + 1) & 1, rr, qq, aP, av, bP, (it + 1) * 32);\
        if (it + 1 < (NITER)) cp_wait<1>(); else cp_wait<0>();                  \
        __syncthreads();                                                        \
        compute_k32f(sm + (it & 1) * STAGE_F, sm + 2 * STAGE_F + (it & 1) * STAGE_F, \
                     wm, wn, g, tig, acc);                                      \
        __syncthreads();                                                        \
    }

// ---------------- K0: init counters ----------------------------------------
__global__ void init_kernel() {
    int t = threadIdx.x;
    if (t < NEXP) { g_counts[t] = 0; g_cursor[t] = 0; }
}

// ---------------- K1: router logits (fp32 SIMT, exact routing) -------------
__global__ __launch_bounds__(256) void router_kernel(
    const float* __restrict__ x, const float* __restrict__ rw,
    const float* __restrict__ rb) {
    __shared__ float xs[8 * DIM];
    int tok0 = blockIdx.x * 8;
    int t = threadIdx.x;
#pragma unroll
    for (int i = 0; i < 8; i++) {
        int s = t + i * 256;
        int r = s >> 8; int q = s & 255;
        *(float4*)(xs + r * DIM + q * 4) =
            *(const float4*)(x + (size_t)(tok0 + r) * DIM + q * 4);
    }
    __syncthreads();
    int tl = t >> 5, e = t & 31;
    float acc = rb[e];
    const float4* xv = (const float4*)(xs + tl * DIM);
    const float4* wv = (const float4*)(rw + (size_t)e * DIM);
#pragma unroll 4
    for (int q = 0; q < DIM / 4; q++) {
        float4 a = xv[q], b = wv[q];
        acc = fmaf(a.x, b.x, acc); acc = fmaf(a.y, b.y, acc);
        acc = fmaf(a.z, b.z, acc); acc = fmaf(a.w, b.w, acc);
    }
    g_logits[(size_t)(tok0 + tl) * NEXP + e] = acc;
}

// ---------------- K2: softmax + top4 + renormalize --------------------------
__global__ __launch_bounds__(256) void topk_kernel() {
    int warp = threadIdx.x >> 5;
    int lane = threadIdx.x & 31;
    int tok = blockIdx.x * 8 + warp;
    float l = g_logits[(size_t)tok * NEXP + lane];
    float m = l;
#pragma unroll
    for (int o = 16; o; o >>= 1) m = fmaxf(m, __shfl_xor_sync(~0u, m, o));
    float p = __expf(l - m);
    float s = p;
#pragma unroll
    for (int o = 16; o; o >>= 1) s += __shfl_xor_sync(~0u, s, o);
    float sc = p / s;

    float cs[TK]; int ci[TK];
    float cur = sc;
#pragma unroll
    for (int t = 0; t < TK; t++) {
        float v = cur; int vi = lane;
#pragma unroll
        for (int o = 16; o; o >>= 1) {
            float ov = __shfl_xor_sync(~0u, v, o);
            int   oi = __shfl_xor_sync(~0u, vi, o);
            if (ov > v || (ov == v && oi < vi)) { v = ov; vi = oi; }
        }
        cs[t] = v; ci[t] = vi;
        if (lane == vi) cur = -1.f;
    }
    float ssum = cs[0] + cs[1] + cs[2] + cs[3];
    float inv = 1.f / fmaxf(ssum, 1e-12f);
    if (lane < TK) {
        g_topk_idx[tok * TK + lane] = ci[lane];
        g_topk_sc [tok * TK + lane] = cs[lane] * inv;
        atomicAdd(&g_counts[ci[lane]], 1);
    }
}

// ---------------- K3: scan ---------------------------------------------------
__global__ void scan_kernel() {
    if (threadIdx.x == 0) {
        int acc = 0;
        g_offsets[0] = 0;
        for (int e = 0; e < NEXP; e++) { acc += g_counts[e]; g_offsets[e + 1] = acc; }
    }
    __syncthreads();
    if (threadIdx.x < NEXP) g_cursor[threadIdx.x] = g_offsets[threadIdx.x];
}

// ---------------- K4: scatter ------------------------------------------------
__global__ __launch_bounds__(256) void scatter_kernel() {
    int i = blockIdx.x * 256 + threadIdx.x;
    int e = g_topk_idx[i];
    int pos = atomicAdd(&g_cursor[e], 1);
    g_bucket_tok[pos] = i >> 2;
    g_bucket_sc [pos] = g_topk_sc[i];
    g_tok_pos[i] = pos;
}

// ---------------- K5: routed gate/up GEMM (pipelined tf32, gather-A) --------
__global__ __launch_bounds__(256) void moe_gu_kernel(
    const float* __restrict__ x, const float* __restrict__ gw,
    const float* __restrict__ uw) {
    int e = blockIdx.y;
    int off = g_offsets[e], cnt = g_offsets[e + 1] - off;
    int tile0 = blockIdx.x * 128;
    if (tile0 >= cnt) return;
    const float* W = (blockIdx.z == 0 ? gw : uw) + (size_t)e * HID * DIM;
    float* OUT = (blockIdx.z == 0 ? g_G : g_U);
    extern __shared__ float sm[];
    __shared__ int toks[128];
    int t = threadIdx.x;
    if (t < 128) { int m = tile0 + t; toks[t] = (m < cnt) ? g_bucket_tok[off + m] : -1; }
    __syncthreads();

    int rr[4], qq[4]; const float* aP[4]; const float* bP[4]; bool av[4];
#pragma unroll
    for (int i = 0; i < 4; i++) {
        int s = t + i * 256; rr[i] = s >> 3; qq[i] = s & 7;
        int tok = toks[rr[i]];
        av[i] = tok >= 0;
        aP[i] = x + (size_t)(av[i] ? tok : 0) * DIM + qq[i] * 4;
        bP[i] = W + (size_t)rr[i] * DIM + qq[i] * 4;
    }
    uint32_t sA = s2u(sm), sB = s2u(sm + 2 * STAGE_F);
    int lane = t & 31, wid = t >> 5;
    int wm = (wid & 3) * 32, wn = (wid >> 2) * 64, g = lane >> 2, tig = lane & 3;
    float acc[2][8][4] = {};

    PIPE_LOOP(DIM / 32)

#pragma unroll
    for (int mt = 0; mt < 2; mt++) {
        int rA = tile0 + wm + mt * 16 + g;
#pragma unroll
        for (int nt = 0; nt < 8; nt++) {
            int col = wn + nt * 8 + 2 * tig;
            if (rA < cnt)
                *(float2*)(OUT + (size_t)(off + rA) * HID + col) =
                    make_float2(acc[mt][nt][0], acc[mt][nt][1]);
            if (rA + 8 < cnt)
                *(float2*)(OUT + (size_t)(off + rA + 8) * HID + col) =
                    make_float2(acc[mt][nt][2], acc[mt][nt][3]);
        }
    }
}

// ---------------- K6: elementwise SiLU(g)*u ----------------------------------
__global__ __launch_bounds__(256) void act_kernel(int which) {
    size_t i = (size_t)blockIdx.x * 256 + threadIdx.x;
    const float4* G = which ? (const float4*)g_sG : (const float4*)g_G;
    const float4* U = which ? (const float4*)g_sU : (const float4*)g_U;
    float4* H = which ? (float4*)g_sH : (float4*)g_H;
    float4 gv = G[i], uv = U[i], h;
    h.x = gv.x / (1.f + __expf(-gv.x)) * uv.x;
    h.y = gv.y / (1.f + __expf(-gv.y)) * uv.y;
    h.z = gv.z / (1.f + __expf(-gv.z)) * uv.z;
    h.w = gv.w / (1.f + __expf(-gv.w)) * uv.w;
    H[i] = h;
}

// ---------------- K7: routed down GEMM (pipelined tf32), scaled -> Y --------
__global__ __launch_bounds__(256) void moe_down_kernel(const float* __restrict__ dw) {
    int e = blockIdx.z;
    int off = g_offsets[e], cnt = g_offsets[e + 1] - off;
    int tile0 = blockIdx.x * 128;
    if (tile0 >= cnt) return;
    int nb = blockIdx.y * 128;
    const float* W = dw + (size_t)e * DIM * HID;
    extern __shared__ float sm[];
    __shared__ float scs[128];
    int t = threadIdx.x;
    if (t < 128) { int m = tile0 + t; scs[t] = (m < cnt) ? g_bucket_sc[off + m] : 0.f; }

    int rr[4], qq[4]; const float* aP[4]; const float* bP[4]; bool av[4];
#pragma unroll
    for (int i = 0; i < 4; i++) {
        int s = t + i * 256; rr[i] = s >> 3; qq[i] = s & 7;
        int m = tile0 + rr[i];
        av[i] = m < cnt;
        aP[i] = g_H + (size_t)(off + (av[i] ? m : 0)) * HID + qq[i] * 4;
        bP[i] = W + (size_t)(nb + rr[i]) * HID + qq[i] * 4;
    }
    uint32_t sA = s2u(sm), sB = s2u(sm + 2 * STAGE_F);
    int lane = t & 31, wid = t >> 5;
    int wm = (wid & 3) * 32, wn = (wid >> 2) * 64, g = lane >> 2, tig = lane & 3;
    float acc[2][8][4] = {};

    PIPE_LOOP(HID / 32)

#pragma unroll
    for (int mt = 0; mt < 2; mt++) {
        int rL = wm + mt * 16 + g;
        int rA = tile0 + rL;
#pragma unroll
        for (int nt = 0; nt < 8; nt++) {
            int col = nb + wn + nt * 8 + 2 * tig;
            if (rA < cnt) {
                float s = scs[rL];
                *(float2*)(g_Y + (size_t)(off + rA) * DIM + col) =
                    make_float2(acc[mt][nt][0] * s, acc[mt][nt][1] * s);
            }
            if (rA + 8 < cnt) {
                float s = scs[rL + 8];
                *(float2*)(g_Y + (size_t)(off + rA + 8) * DIM + col) =
                    make_float2(acc[mt][nt][2] * s, acc[mt][nt][3] * s);
            }
        }
    }
}

// ---------------- K8: shared gate/up GEMM (pipelined tf32) -------------------
__global__ __launch_bounds__(256) void shared_gu_kernel(
    const float* __restrict__ x, const float* __restrict__ sgw,
    const float* __restrict__ suw) {
    int tile0 = blockIdx.x * 128;
    int nb = blockIdx.y * 128;
    const float* W = (blockIdx.z == 0 ? sgw : suw);
    float* OUT = (blockIdx.z == 0 ? g_sG : g_sU);
    extern __shared__ float sm[];
    int t = threadIdx.x;

    int rr[4], qq[4]; const float* aP[4]; const float* bP[4]; bool av[4];
#pragma unroll
    for (int i = 0; i < 4; i++) {
        int s = t + i * 256; rr[i] = s >> 3; qq[i] = s & 7;
        av[i] = true;
        aP[i] = x + (size_t)(tile0 + rr[i]) * DIM + qq[i] * 4;
        bP[i] = W + (size_t)(nb + rr[i]) * DIM + qq[i] * 4;
    }
    uint32_t sA = s2u(sm), sB = s2u(sm + 2 * STAGE_F);
    int lane = t & 31, wid = t >> 5;
    int wm = (wid & 3) * 32, wn = (wid >> 2) * 64, g = lane >> 2, tig = lane & 3;
    float acc[2][8][4] = {};

    PIPE_LOOP(DIM / 32)

#pragma unroll
    for (int mt = 0; mt < 2; mt++) {
        int rA = tile0 + wm + mt * 16 + g;
#pragma unroll
        for (int nt = 0; nt < 8; nt++) {
            int col = nb + wn + nt * 8 + 2 * tig;
            *(float2*)(OUT + (size_t)rA * SHID + col) = make_float2(acc[mt][nt][0], acc[mt][nt][1]);
            *(float2*)(OUT + (size_t)(rA + 8) * SHID + col) = make_float2(acc[mt][nt][2], acc[mt][nt][3]);
        }
    }
}

// ---------------- K9: final GEMM + Y gather (pipelined tf32) -----------------
__global__ __launch_bounds__(256) void final_kernel(
    const float* __restrict__ sdw, float* __restrict__ out) {
    int tile0 = blockIdx.x * 128;
    int nb = blockIdx.y * 128;
    extern __shared__ float sm[];
    int t = threadIdx.x;

    int rr[4], qq[4]; const float* aP[4]; const float* bP[4]; bool av[4];
#pragma unroll
    for (int i = 0; i < 4; i++) {
        int s = t + i * 256; rr[i] = s >> 3; qq[i] = s & 7;
        av[i] = true;
        aP[i] = g_sH + (size_t)(tile0 + rr[i]) * SHID + qq[i] * 4;
        bP[i] = sdw + (size_t)(nb + rr[i]) * SHID + qq[i] * 4;
    }
    uint32_t sA = s2u(sm), sB = s2u(sm + 2 * STAGE_F);
    int lane = t & 31, wid = t >> 5;
    int wm = (wid & 3) * 32, wn = (wid >> 2) * 64, g = lane >> 2, tig = lane & 3;
    float acc[2][8][4] = {};

    PIPE_LOOP(SHID / 32)

#pragma unroll
    for (int mt = 0; mt < 2; mt++) {
        int r0 = tile0 + wm + mt * 16 + g;
        int4 tpa = *(const int4*)(g_tok_pos + r0 * TK);
        int4 tpb = *(const int4*)(g_tok_pos + (r0 + 8) * TK);
#pragma unroll
        for (int nt = 0; nt < 8; nt++) {
            int col = nb + wn + nt * 8 + 2 * tig;
            float2 y0 = *(const float2*)(g_Y + (size_t)tpa.x * DIM + col);
            float2 y1 = *(const float2*)(g_Y + (size_t)tpa.y * DIM + col);
            float2 y2 = *(const float2*)(g_Y + (size_t)tpa.z * DIM + col);
            float2 y3 = *(const float2*)(g_Y + (size_t)tpa.w * DIM + col);
            float2 ra;
            ra.x = acc[mt][nt][0] + y0.x + y1.x + y2.x + y3.x;
            ra.y = acc[mt][nt][1] + y0.y + y1.y + y2.y + y3.y;
            *(float2*)(out + (size_t)r0 * DIM + col) = ra;
            float2 z0 = *(const float2*)(g_Y + (size_t)tpb.x * DIM + col);
            float2 z1 = *(const float2*)(g_Y + (size_t)tpb.y * DIM + col);
            float2 z2 = *(const float2*)(g_Y + (size_t)tpb.z * DIM + col);
            float2 z3 = *(const float2*)(g_Y + (size_t)tpb.w * DIM + col);
            float2 rb;
            rb.x = acc[mt][nt][2] + z0.x + z1.x + z2.x + z3.x;
            rb.y = acc[mt][nt][3] + z0.y + z1.y + z2.y + z3.y;
            *(float2*)(out + (size_t)(r0 + 8) * DIM + col) = rb;
        }
    }
}

// ---------------- launch ------------------------------------------------------
extern "C" void kernel_launch(void* const* d_in, const int* in_sizes, int n_in,
                              void* d_out, int out_size) {
    const float* x   = (const float*)d_in[0];
    const float* rw  = (const float*)d_in[1];
    const float* rb  = (const float*)d_in[2];
    const float* gw  = (const float*)d_in[3];
    const float* uw  = (const float*)d_in[4];
    const float* dw  = (const float*)d_in[5];
    const float* sgw = (const float*)d_in[6];
    const float* suw = (const float*)d_in[7];
    const float* sdw = (const float*)d_in[8];
    float* out = (float*)d_out;

    cudaFuncSetAttribute(moe_gu_kernel,    cudaFuncAttributeMaxDynamicSharedMemorySize, SMEM_PIPE_BYTES);
    cudaFuncSetAttribute(moe_down_kernel,  cudaFuncAttributeMaxDynamicSharedMemorySize, SMEM_PIPE_BYTES);
    cudaFuncSetAttribute(shared_gu_kernel, cudaFuncAttributeMaxDynamicSharedMemorySize, SMEM_PIPE_BYTES);
    cudaFuncSetAttribute(final_kernel,     cudaFuncAttributeMaxDynamicSharedMemorySize, SMEM_PIPE_BYTES);

    init_kernel<<<1, 32>>>();
    router_kernel<<<NTOK / 8, 256>>>(x, rw, rb);
    topk_kernel<<<NTOK / 8, 256>>>();
    scan_kernel<<<1, 32>>>();
    scatter_kernel<<<NROWS / 256, 256>>>();
    moe_gu_kernel<<<dim3(64, NEXP, 2), 256, SMEM_PIPE_BYTES>>>(x, gw, uw);
    act_kernel<<<(NROWS * HID) / 4 / 256, 256>>>(0);
    moe_down_kernel<<<dim3(64, 8, NEXP), 256, SMEM_PIPE_BYTES>>>(dw);
    shared_gu_kernel<<<dim3(64, 4, 2), 256, SMEM_PIPE_BYTES>>>(x, sgw, suw);
    act_kernel<<<((size_t)NTOK * SHID) / 4 / 256, 256>>>(1);
    final_kernel<<<dim3(64, 8), 256, SMEM_PIPE_BYTES>>>(sdw, out);
}